// round 11
// baseline (speedup 1.0000x reference)
#include <cuda_runtime.h>

#define N_NODES 8192
#define NV4 (N_NODES / 4)       // 2048 float4 per row
#define PSI 64
#define THREADS_RS 512
#define GRID_RS 444             // 148 SMs x 3 blocks, grid-stride over rows

// __device__ scratch (no allocations allowed).
// g_agg zero-init at load; node_mlp reads-then-zeros it each replay.
__device__ float g_agg[N_NODES];
__device__ float g_t[N_NODES];
__device__ float g_s[N_NODES];

// ---------------------------------------------------------------------------
// Kernel 1: edge MLP + scatter-add by col.
// Algebraic fast path (zero hidden bias, verified on device):
//   f(v) = v*Cp + b2  (v >= 0),   f(v) = v*Cn + b2  (v < 0).
// Generic 64-term fallback keeps the kernel exact for arbitrary inputs.
// ---------------------------------------------------------------------------
__global__ __launch_bounds__(256) void k_edge_scatter(
        const int* __restrict__ col,
        const float* __restrict__ values,
        const float* __restrict__ w1,
        const float* __restrict__ b1,
        const float* __restrict__ w2,
        const float* __restrict__ b2,
        int nnz) {
    __shared__ float sw1[PSI], sb1[PSI], sw2[PSI];
    __shared__ float sCp, sCn, sb2;
    __shared__ int sfast;
    if (threadIdx.x < PSI) {
        sw1[threadIdx.x] = w1[threadIdx.x];
        sb1[threadIdx.x] = b1[threadIdx.x];
        sw2[threadIdx.x] = w2[threadIdx.x];
    }
    if (threadIdx.x == 0) sb2 = b2[0];
    __syncthreads();
    if (threadIdx.x == 0) {
        float cp = 0.0f, cn = 0.0f;
        int ok = 1;
#pragma unroll
        for (int j = 0; j < PSI; j++) {
            float w = sw1[j];
            float p = w * sw2[j];
            if (w > 0.0f) cp += p;
            else if (w < 0.0f) cn += p;
            if (sb1[j] != 0.0f) ok = 0;
        }
        sCp = cp; sCn = cn; sfast = ok;
    }
    __syncthreads();

    int i = blockIdx.x * 256 + threadIdx.x;
    if (i >= nnz) return;
    float v = values[i];
    float feat;
    if (sfast) {
        feat = fmaf(v, (v >= 0.0f) ? sCp : sCn, sb2);
    } else {
        float p0 = 0.0f, p1 = 0.0f, p2 = 0.0f, p3 = 0.0f;
#pragma unroll
        for (int j = 0; j < PSI; j += 4) {
            p0 = fmaf(fmaxf(fmaf(v, sw1[j+0], sb1[j+0]), 0.0f), sw2[j+0], p0);
            p1 = fmaf(fmaxf(fmaf(v, sw1[j+1], sb1[j+1]), 0.0f), sw2[j+1], p1);
            p2 = fmaf(fmaxf(fmaf(v, sw1[j+2], sb1[j+2]), 0.0f), sw2[j+2], p2);
            p3 = fmaf(fmaxf(fmaf(v, sw1[j+3], sb1[j+3]), 0.0f), sw2[j+3], p3);
        }
        feat = sb2 + (p0 + p1) + (p2 + p3);
    }
    atomicAdd(&g_agg[col[i]], feat);
}

// ---------------------------------------------------------------------------
// Kernel 2: node MLP, store struct^2, re-zero g_agg for the next replay.
// PDL secondary.
// ---------------------------------------------------------------------------
__global__ __launch_bounds__(512) void k_node_mlp(
        const float* __restrict__ w1,
        const float* __restrict__ b1,
        const float* __restrict__ w2,
        const float* __restrict__ b2) {
    __shared__ float sw1[PSI], sb1[PSI], sw2[PSI], sb2;
    if (threadIdx.x < PSI) {
        sw1[threadIdx.x] = w1[threadIdx.x];
        sb1[threadIdx.x] = b1[threadIdx.x];
        sw2[threadIdx.x] = w2[threadIdx.x];
    }
    if (threadIdx.x == 0) sb2 = b2[0];
    __syncthreads();

    cudaGridDependencySynchronize();   // all g_agg atomics visible

    int i = blockIdx.x * 512 + threadIdx.x;
    if (i >= N_NODES) return;
    float x = g_agg[i];
    g_agg[i] = 0.0f;              // reset for next graph replay
    float p0 = 0.0f, p1 = 0.0f, p2 = 0.0f, p3 = 0.0f;
#pragma unroll
    for (int j = 0; j < PSI; j += 4) {
        p0 = fmaf(fmaxf(fmaf(x, sw1[j+0], sb1[j+0]), 0.0f), sw2[j+0], p0);
        p1 = fmaf(fmaxf(fmaf(x, sw1[j+1], sb1[j+1]), 0.0f), sw2[j+1], p1);
        p2 = fmaf(fmaxf(fmaf(x, sw1[j+2], sb1[j+2]), 0.0f), sw2[j+2], p2);
        p3 = fmaf(fmaxf(fmaf(x, sw1[j+3], sb1[j+3]), 0.0f), sw2[j+3], p3);
    }
    float acc = sb2 + (p0 + p1) + (p2 + p3);
    g_t[i] = acc * acc;
}

// ---------------------------------------------------------------------------
// Kernel 3: row score.  s[r] = sum_n adj[r,n]^2 * t[n]
// 512 threads, 3 blocks/SM (grid 444), grid-stride rows.  Each thread owns a
// FIXED column subset (i = tid + k*512), so its 4 float4 of t are hoisted
// into registers ONCE and reused for all ~18 rows the block processes:
// the inner loop is pure adj streaming (__ldcs) + FMA — no second load.
// PDL secondary.
// ---------------------------------------------------------------------------
__global__ __launch_bounds__(THREADS_RS, 3) void k_row_score(
        const float* __restrict__ adj) {
    __shared__ float warp_sum[16];

    cudaGridDependencySynchronize();   // g_t ready

    const int tid = threadIdx.x;
    const float4* __restrict__ tv = reinterpret_cast<const float4*>(g_t);
    const float4 tw0 = tv[tid];
    const float4 tw1 = tv[tid + 512];
    const float4 tw2 = tv[tid + 1024];
    const float4 tw3 = tv[tid + 1536];

    const int lane = tid & 31;
    const int wid  = tid >> 5;

    for (int row = blockIdx.x; row < N_NODES; row += GRID_RS) {
        const float4* __restrict__ a =
            reinterpret_cast<const float4*>(adj + (size_t)row * N_NODES);
        float4 v0 = __ldcs(&a[tid]);
        float4 v1 = __ldcs(&a[tid + 512]);
        float4 v2 = __ldcs(&a[tid + 1024]);
        float4 v3 = __ldcs(&a[tid + 1536]);

        float acc;
        acc  = v0.x * v0.x * tw0.x;
        acc  = fmaf(v0.y * v0.y, tw0.y, acc);
        acc  = fmaf(v0.z * v0.z, tw0.z, acc);
        acc  = fmaf(v0.w * v0.w, tw0.w, acc);
        acc  = fmaf(v1.x * v1.x, tw1.x, acc);
        acc  = fmaf(v1.y * v1.y, tw1.y, acc);
        acc  = fmaf(v1.z * v1.z, tw1.z, acc);
        acc  = fmaf(v1.w * v1.w, tw1.w, acc);
        acc  = fmaf(v2.x * v2.x, tw2.x, acc);
        acc  = fmaf(v2.y * v2.y, tw2.y, acc);
        acc  = fmaf(v2.z * v2.z, tw2.z, acc);
        acc  = fmaf(v2.w * v2.w, tw2.w, acc);
        acc  = fmaf(v3.x * v3.x, tw3.x, acc);
        acc  = fmaf(v3.y * v3.y, tw3.y, acc);
        acc  = fmaf(v3.z * v3.z, tw3.z, acc);
        acc  = fmaf(v3.w * v3.w, tw3.w, acc);

#pragma unroll
        for (int off = 16; off > 0; off >>= 1)
            acc += __shfl_down_sync(0xffffffffu, acc, off);
        if (lane == 0) warp_sum[wid] = acc;
        __syncthreads();
        if (tid < 16) {
            float v = warp_sum[tid];
#pragma unroll
            for (int off = 8; off > 0; off >>= 1)
                v += __shfl_down_sync(0xffffu, v, off);
            if (tid == 0) g_s[row] = v;
        }
        __syncthreads();   // warp_sum reuse next row
    }
}

// ---------------------------------------------------------------------------
// Kernel 4: gather per-edge output, 1 edge/thread, 256 small blocks for SM
// spread (g_s is L2-hot).  PDL secondary.
// ---------------------------------------------------------------------------
__global__ __launch_bounds__(128) void k_gather(const int* __restrict__ src_nodes,
                                                float* __restrict__ out, int E) {
    int e = blockIdx.x * 128 + threadIdx.x;
    cudaGridDependencySynchronize();   // g_s ready
    if (e < E) out[e] = g_s[src_nodes[e]];
}

// ---------------------------------------------------------------------------
// launch helper: PDL launch (programmatic stream serialization)
// ---------------------------------------------------------------------------
template <typename... Args>
static inline void launch_pdl(void (*kern)(Args...), dim3 grid, dim3 block,
                              Args... args) {
    cudaLaunchAttribute attr[1];
    attr[0].id = cudaLaunchAttributeProgrammaticStreamSerialization;
    attr[0].val.programmaticStreamSerializationAllowed = 1;
    cudaLaunchConfig_t cfg{};
    cfg.gridDim = grid;
    cfg.blockDim = block;
    cfg.dynamicSmemBytes = 0;
    cfg.stream = 0;
    cfg.attrs = attr;
    cfg.numAttrs = 1;
    cudaLaunchKernelEx(&cfg, kern, args...);
}

// ---------------------------------------------------------------------------
// launch
// Inputs (metadata order): col, values, adj, src_nodes,
//                          w1e, b1e, w2e, b2e, w1n, b1n, w2n, b2n
// ---------------------------------------------------------------------------
extern "C" void kernel_launch(void* const* d_in, const int* in_sizes, int n_in,
                              void* d_out, int out_size) {
    const int*   col       = (const int*)d_in[0];
    const float* values    = (const float*)d_in[1];
    const float* adj       = (const float*)d_in[2];
    const int*   src_nodes = (const int*)d_in[3];
    const float* w1e = (const float*)d_in[4];
    const float* b1e = (const float*)d_in[5];
    const float* w2e = (const float*)d_in[6];
    const float* b2e = (const float*)d_in[7];
    const float* w1n = (const float*)d_in[8];
    const float* b1n = (const float*)d_in[9];
    const float* w2n = (const float*)d_in[10];
    const float* b2n = (const float*)d_in[11];
    float* out = (float*)d_out;

    const int nnz = in_sizes[0];   // 262144
    const int E   = in_sizes[3];   // 32768

    // primary: plain launch
    k_edge_scatter<<<(nnz + 255) / 256, 256>>>(
        col, values, w1e, b1e, w2e, b2e, nnz);

    // dependents: PDL
    launch_pdl(k_node_mlp, dim3((N_NODES + 511) / 512), dim3(512),
               w1n, b1n, w2n, b2n);
    launch_pdl(k_row_score, dim3(GRID_RS), dim3(THREADS_RS), adj);
    launch_pdl(k_gather, dim3((E + 127) / 128), dim3(128),
               src_nodes, out, E);
}

// round 12
// speedup vs baseline: 1.0640x; 1.0640x over previous
#include <cuda_runtime.h>

#define N_NODES 8192
#define NV4 (N_NODES / 4)       // 2048 float4 per row
#define PSI 64
#define GRID_RS 1184            // 148 SMs x 8 blocks, grid-stride over rows

// __device__ scratch (no allocations allowed).
// g_agg zero-init at load; node_mlp reads-then-zeros it each replay.
// g_s accumulated by atomics in row_score; node_mlp zeroes it each replay
// (node_mlp always precedes row_score in the serialized chain).
__device__ float g_agg[N_NODES];
__device__ float g_t[N_NODES];
__device__ float g_s[N_NODES];

// ---------------------------------------------------------------------------
// Kernel 1: edge MLP + scatter-add by col.
// Algebraic fast path (zero hidden bias, verified on device):
//   f(v) = v*Cp + b2  (v >= 0),   f(v) = v*Cn + b2  (v < 0).
// Generic 64-term fallback keeps the kernel exact for arbitrary inputs.
// ---------------------------------------------------------------------------
__global__ __launch_bounds__(256) void k_edge_scatter(
        const int* __restrict__ col,
        const float* __restrict__ values,
        const float* __restrict__ w1,
        const float* __restrict__ b1,
        const float* __restrict__ w2,
        const float* __restrict__ b2,
        int nnz) {
    __shared__ float sw1[PSI], sb1[PSI], sw2[PSI];
    __shared__ float sCp, sCn, sb2;
    __shared__ int sfast;
    if (threadIdx.x < PSI) {
        sw1[threadIdx.x] = w1[threadIdx.x];
        sb1[threadIdx.x] = b1[threadIdx.x];
        sw2[threadIdx.x] = w2[threadIdx.x];
    }
    if (threadIdx.x == 0) sb2 = b2[0];
    __syncthreads();
    if (threadIdx.x == 0) {
        float cp = 0.0f, cn = 0.0f;
        int ok = 1;
#pragma unroll
        for (int j = 0; j < PSI; j++) {
            float w = sw1[j];
            float p = w * sw2[j];
            if (w > 0.0f) cp += p;
            else if (w < 0.0f) cn += p;
            if (sb1[j] != 0.0f) ok = 0;
        }
        sCp = cp; sCn = cn; sfast = ok;
    }
    __syncthreads();

    int i = blockIdx.x * 256 + threadIdx.x;
    if (i >= nnz) return;
    float v = values[i];
    float feat;
    if (sfast) {
        feat = fmaf(v, (v >= 0.0f) ? sCp : sCn, sb2);
    } else {
        float p0 = 0.0f, p1 = 0.0f, p2 = 0.0f, p3 = 0.0f;
#pragma unroll
        for (int j = 0; j < PSI; j += 4) {
            p0 = fmaf(fmaxf(fmaf(v, sw1[j+0], sb1[j+0]), 0.0f), sw2[j+0], p0);
            p1 = fmaf(fmaxf(fmaf(v, sw1[j+1], sb1[j+1]), 0.0f), sw2[j+1], p1);
            p2 = fmaf(fmaxf(fmaf(v, sw1[j+2], sb1[j+2]), 0.0f), sw2[j+2], p2);
            p3 = fmaf(fmaxf(fmaf(v, sw1[j+3], sb1[j+3]), 0.0f), sw2[j+3], p3);
        }
        feat = sb2 + (p0 + p1) + (p2 + p3);
    }
    atomicAdd(&g_agg[col[i]], feat);
}

// ---------------------------------------------------------------------------
// Kernel 2: node MLP, store struct^2, re-zero g_agg AND g_s for the next
// phase/replay.  PDL secondary.
// ---------------------------------------------------------------------------
__global__ __launch_bounds__(512) void k_node_mlp(
        const float* __restrict__ w1,
        const float* __restrict__ b1,
        const float* __restrict__ w2,
        const float* __restrict__ b2) {
    __shared__ float sw1[PSI], sb1[PSI], sw2[PSI], sb2;
    if (threadIdx.x < PSI) {
        sw1[threadIdx.x] = w1[threadIdx.x];
        sb1[threadIdx.x] = b1[threadIdx.x];
        sw2[threadIdx.x] = w2[threadIdx.x];
    }
    if (threadIdx.x == 0) sb2 = b2[0];
    __syncthreads();

    cudaGridDependencySynchronize();   // all g_agg atomics visible

    int i = blockIdx.x * 512 + threadIdx.x;
    if (i >= N_NODES) return;
    float x = g_agg[i];
    g_agg[i] = 0.0f;              // reset for next graph replay
    g_s[i]   = 0.0f;              // row_score accumulates atomically into g_s
    float p0 = 0.0f, p1 = 0.0f, p2 = 0.0f, p3 = 0.0f;
#pragma unroll
    for (int j = 0; j < PSI; j += 4) {
        p0 = fmaf(fmaxf(fmaf(x, sw1[j+0], sb1[j+0]), 0.0f), sw2[j+0], p0);
        p1 = fmaf(fmaxf(fmaf(x, sw1[j+1], sb1[j+1]), 0.0f), sw2[j+1], p1);
        p2 = fmaf(fmaxf(fmaf(x, sw1[j+2], sb1[j+2]), 0.0f), sw2[j+2], p2);
        p3 = fmaf(fmaxf(fmaf(x, sw1[j+3], sb1[j+3]), 0.0f), sw2[j+3], p3);
    }
    float acc = sb2 + (p0 + p1) + (p2 + p3);
    g_t[i] = acc * acc;
}

// ---------------------------------------------------------------------------
// Kernel 3: row score.  s[r] = sum_n adj[r,n]^2 * t[n]
// Grid-stride over rows, grid = 1184 (8 blocks/SM, 2048 thr/SM).  R10's
// proven streaming body, but NO block barriers in the row loop: warp-shuffle
// reduce then one atomicAdd per warp per row (8 REDG/row).  Warps run fully
// decoupled, so next-row loads overlap other warps' reductions.
// PDL secondary.
// ---------------------------------------------------------------------------
__global__ __launch_bounds__(256, 8) void k_row_score(const float* __restrict__ adj) {
    const float4* __restrict__ tv = reinterpret_cast<const float4*>(g_t);

    cudaGridDependencySynchronize();   // g_t ready, g_s zeroed

    for (int row = blockIdx.x; row < N_NODES; row += GRID_RS) {
        const float4* __restrict__ a =
            reinterpret_cast<const float4*>(adj + (size_t)row * N_NODES);
        float acc = 0.0f;
#pragma unroll 4
        for (int i = threadIdx.x; i < NV4; i += 256) {
            float4 av = __ldcs(&a[i]);
            float4 tw = __ldg(&tv[i]);
            acc = fmaf(av.x * av.x, tw.x, acc);
            acc = fmaf(av.y * av.y, tw.y, acc);
            acc = fmaf(av.z * av.z, tw.z, acc);
            acc = fmaf(av.w * av.w, tw.w, acc);
        }
#pragma unroll
        for (int off = 16; off > 0; off >>= 1)
            acc += __shfl_down_sync(0xffffffffu, acc, off);
        if ((threadIdx.x & 31) == 0)
            atomicAdd(&g_s[row], acc);
    }
}

// ---------------------------------------------------------------------------
// Kernel 4: gather per-edge output (g_s is L2-hot).  PDL secondary.
// ---------------------------------------------------------------------------
__global__ __launch_bounds__(256) void k_gather(const int* __restrict__ src_nodes,
                                                float* __restrict__ out, int E) {
    int e = blockIdx.x * 256 + threadIdx.x;
    cudaGridDependencySynchronize();   // g_s atomics complete
    if (e < E) out[e] = g_s[src_nodes[e]];
}

// ---------------------------------------------------------------------------
// launch helper: PDL launch (programmatic stream serialization)
// ---------------------------------------------------------------------------
template <typename... Args>
static inline void launch_pdl(void (*kern)(Args...), dim3 grid, dim3 block,
                              Args... args) {
    cudaLaunchAttribute attr[1];
    attr[0].id = cudaLaunchAttributeProgrammaticStreamSerialization;
    attr[0].val.programmaticStreamSerializationAllowed = 1;
    cudaLaunchConfig_t cfg{};
    cfg.gridDim = grid;
    cfg.blockDim = block;
    cfg.dynamicSmemBytes = 0;
    cfg.stream = 0;
    cfg.attrs = attr;
    cfg.numAttrs = 1;
    cudaLaunchKernelEx(&cfg, kern, args...);
}

// ---------------------------------------------------------------------------
// launch
// Inputs (metadata order): col, values, adj, src_nodes,
//                          w1e, b1e, w2e, b2e, w1n, b1n, w2n, b2n
// ---------------------------------------------------------------------------
extern "C" void kernel_launch(void* const* d_in, const int* in_sizes, int n_in,
                              void* d_out, int out_size) {
    const int*   col       = (const int*)d_in[0];
    const float* values    = (const float*)d_in[1];
    const float* adj       = (const float*)d_in[2];
    const int*   src_nodes = (const int*)d_in[3];
    const float* w1e = (const float*)d_in[4];
    const float* b1e = (const float*)d_in[5];
    const float* w2e = (const float*)d_in[6];
    const float* b2e = (const float*)d_in[7];
    const float* w1n = (const float*)d_in[8];
    const float* b1n = (const float*)d_in[9];
    const float* w2n = (const float*)d_in[10];
    const float* b2n = (const float*)d_in[11];
    float* out = (float*)d_out;

    const int nnz = in_sizes[0];   // 262144
    const int E   = in_sizes[3];   // 32768

    // primary: plain launch
    k_edge_scatter<<<(nnz + 255) / 256, 256>>>(
        col, values, w1e, b1e, w2e, b2e, nnz);

    // dependents: PDL
    launch_pdl(k_node_mlp, dim3((N_NODES + 511) / 512), dim3(512),
               w1n, b1n, w2n, b2n);
    launch_pdl(k_row_score, dim3(GRID_RS), dim3(256), adj);
    launch_pdl(k_gather, dim3((E + 255) / 256), dim3(256),
               src_nodes, out, E);
}

// round 13
// speedup vs baseline: 1.0800x; 1.0150x over previous
#include <cuda_runtime.h>

#define N_NODES 8192
#define NV4 (N_NODES / 4)       // 2048 float4 per row
#define PSI 64
#define GRID_RS 1184            // 148 SMs x 8 blocks, grid-stride over rows
#define PREFETCH_ROWS 1024      // 32 MB warmed into L2 during the scatter phase

// __device__ scratch (no allocations allowed).
// g_agg zero-init at load; node_mlp reads-then-zeros it each replay.
__device__ float g_agg[N_NODES];
__device__ float g_t[N_NODES];
__device__ float g_s[N_NODES];
__device__ float g_sink;        // prefetch DCE guard (never actually written)

// ---------------------------------------------------------------------------
// Kernel 0: L2 prefetch of the first PREFETCH_ROWS rows of adj.
// Triggers programmatic completion IMMEDIATELY so the (independent)
// edge_scatter launched behind it starts concurrently; this kernel then
// streams 32 MB into L2 during the otherwise DRAM-idle scatter phase.
// ---------------------------------------------------------------------------
__global__ __launch_bounds__(256) void k_prefetch(const float* __restrict__ adj) {
    cudaTriggerProgrammaticLaunchCompletion();   // release the next kernel now
    const float4* __restrict__ a = reinterpret_cast<const float4*>(adj);
    const int total = PREFETCH_ROWS * NV4;       // 2M float4
    float acc = 0.0f;
    for (int i = blockIdx.x * 256 + threadIdx.x; i < total; i += 512 * 256) {
        float4 v = __ldcg(&a[i]);                // L2-allocating load
        acc += v.x + v.y + v.z + v.w;
    }
    if (acc == -1.2345678e-33f) g_sink = acc;    // keep the loads alive
}

// ---------------------------------------------------------------------------
// Kernel 1: edge MLP + scatter-add by col.
// Algebraic fast path (zero hidden bias, verified on device):
//   f(v) = v*Cp + b2  (v >= 0),   f(v) = v*Cn + b2  (v < 0).
// Generic 64-term fallback keeps the kernel exact for arbitrary inputs.
// Launched with PDL but NO grid-sync: independent of the prefetch.
// ---------------------------------------------------------------------------
__global__ __launch_bounds__(256) void k_edge_scatter(
        const int* __restrict__ col,
        const float* __restrict__ values,
        const float* __restrict__ w1,
        const float* __restrict__ b1,
        const float* __restrict__ w2,
        const float* __restrict__ b2,
        int nnz) {
    __shared__ float sw1[PSI], sb1[PSI], sw2[PSI];
    __shared__ float sCp, sCn, sb2;
    __shared__ int sfast;
    if (threadIdx.x < PSI) {
        sw1[threadIdx.x] = w1[threadIdx.x];
        sb1[threadIdx.x] = b1[threadIdx.x];
        sw2[threadIdx.x] = w2[threadIdx.x];
    }
    if (threadIdx.x == 0) sb2 = b2[0];
    __syncthreads();
    if (threadIdx.x == 0) {
        float cp = 0.0f, cn = 0.0f;
        int ok = 1;
#pragma unroll
        for (int j = 0; j < PSI; j++) {
            float w = sw1[j];
            float p = w * sw2[j];
            if (w > 0.0f) cp += p;
            else if (w < 0.0f) cn += p;
            if (sb1[j] != 0.0f) ok = 0;
        }
        sCp = cp; sCn = cn; sfast = ok;
    }
    __syncthreads();

    int i = blockIdx.x * 256 + threadIdx.x;
    if (i >= nnz) return;
    float v = values[i];
    float feat;
    if (sfast) {
        feat = fmaf(v, (v >= 0.0f) ? sCp : sCn, sb2);
    } else {
        float p0 = 0.0f, p1 = 0.0f, p2 = 0.0f, p3 = 0.0f;
#pragma unroll
        for (int j = 0; j < PSI; j += 4) {
            p0 = fmaf(fmaxf(fmaf(v, sw1[j+0], sb1[j+0]), 0.0f), sw2[j+0], p0);
            p1 = fmaf(fmaxf(fmaf(v, sw1[j+1], sb1[j+1]), 0.0f), sw2[j+1], p1);
            p2 = fmaf(fmaxf(fmaf(v, sw1[j+2], sb1[j+2]), 0.0f), sw2[j+2], p2);
            p3 = fmaf(fmaxf(fmaf(v, sw1[j+3], sb1[j+3]), 0.0f), sw2[j+3], p3);
        }
        feat = sb2 + (p0 + p1) + (p2 + p3);
    }
    atomicAdd(&g_agg[col[i]], feat);
}

// ---------------------------------------------------------------------------
// Kernel 2: node MLP, store struct^2, re-zero g_agg for the next replay.
// PDL secondary (waits on edge_scatter).
// ---------------------------------------------------------------------------
__global__ __launch_bounds__(512) void k_node_mlp(
        const float* __restrict__ w1,
        const float* __restrict__ b1,
        const float* __restrict__ w2,
        const float* __restrict__ b2) {
    __shared__ float sw1[PSI], sb1[PSI], sw2[PSI], sb2;
    if (threadIdx.x < PSI) {
        sw1[threadIdx.x] = w1[threadIdx.x];
        sb1[threadIdx.x] = b1[threadIdx.x];
        sw2[threadIdx.x] = w2[threadIdx.x];
    }
    if (threadIdx.x == 0) sb2 = b2[0];
    __syncthreads();

    cudaGridDependencySynchronize();   // all g_agg atomics visible

    int i = blockIdx.x * 512 + threadIdx.x;
    if (i >= N_NODES) return;
    float x = g_agg[i];
    g_agg[i] = 0.0f;              // reset for next graph replay
    float p0 = 0.0f, p1 = 0.0f, p2 = 0.0f, p3 = 0.0f;
#pragma unroll
    for (int j = 0; j < PSI; j += 4) {
        p0 = fmaf(fmaxf(fmaf(x, sw1[j+0], sb1[j+0]), 0.0f), sw2[j+0], p0);
        p1 = fmaf(fmaxf(fmaf(x, sw1[j+1], sb1[j+1]), 0.0f), sw2[j+1], p1);
        p2 = fmaf(fmaxf(fmaf(x, sw1[j+2], sb1[j+2]), 0.0f), sw2[j+2], p2);
        p3 = fmaf(fmaxf(fmaf(x, sw1[j+3], sb1[j+3]), 0.0f), sw2[j+3], p3);
    }
    float acc = sb2 + (p0 + p1) + (p2 + p3);
    g_t[i] = acc * acc;
}

// ---------------------------------------------------------------------------
// Kernel 3: row score.  s[r] = sum_n adj[r,n]^2 * t[n]
// R10's measured-best body: grid-stride rows, grid 1184 (8 blocks/SM),
// unroll-4 streaming with __ldcs, smem block reduction.  Rows 0..1023 hit
// the L2 lines warmed by k_prefetch.  PDL secondary.
// ---------------------------------------------------------------------------
__global__ __launch_bounds__(256, 8) void k_row_score(const float* __restrict__ adj) {
    __shared__ float warp_sum[8];
    const float4* __restrict__ tv = reinterpret_cast<const float4*>(g_t);

    cudaGridDependencySynchronize();   // g_t ready

    for (int row = blockIdx.x; row < N_NODES; row += GRID_RS) {
        const float4* __restrict__ a =
            reinterpret_cast<const float4*>(adj + (size_t)row * N_NODES);
        float acc = 0.0f;
#pragma unroll 4
        for (int i = threadIdx.x; i < NV4; i += 256) {
            float4 av = __ldcs(&a[i]);
            float4 tw = __ldg(&tv[i]);
            acc = fmaf(av.x * av.x, tw.x, acc);
            acc = fmaf(av.y * av.y, tw.y, acc);
            acc = fmaf(av.z * av.z, tw.z, acc);
            acc = fmaf(av.w * av.w, tw.w, acc);
        }
#pragma unroll
        for (int off = 16; off > 0; off >>= 1)
            acc += __shfl_down_sync(0xffffffffu, acc, off);
        if ((threadIdx.x & 31) == 0) warp_sum[threadIdx.x >> 5] = acc;
        __syncthreads();
        if (threadIdx.x < 8) {
            float v = warp_sum[threadIdx.x];
#pragma unroll
            for (int off = 4; off > 0; off >>= 1)
                v += __shfl_down_sync(0xffu, v, off);
            if (threadIdx.x == 0) g_s[row] = v;
        }
        __syncthreads();   // warp_sum reuse next row
    }
}

// ---------------------------------------------------------------------------
// Kernel 4: gather per-edge output (g_s is L2-hot).  PDL secondary.
// ---------------------------------------------------------------------------
__global__ __launch_bounds__(256) void k_gather(const int* __restrict__ src_nodes,
                                                float* __restrict__ out, int E) {
    int e = blockIdx.x * 256 + threadIdx.x;
    cudaGridDependencySynchronize();   // g_s ready
    if (e < E) out[e] = g_s[src_nodes[e]];
}

// ---------------------------------------------------------------------------
// launch helper: PDL launch (programmatic stream serialization)
// ---------------------------------------------------------------------------
template <typename... Args>
static inline void launch_pdl(void (*kern)(Args...), dim3 grid, dim3 block,
                              Args... args) {
    cudaLaunchAttribute attr[1];
    attr[0].id = cudaLaunchAttributeProgrammaticStreamSerialization;
    attr[0].val.programmaticStreamSerializationAllowed = 1;
    cudaLaunchConfig_t cfg{};
    cfg.gridDim = grid;
    cfg.blockDim = block;
    cfg.dynamicSmemBytes = 0;
    cfg.stream = 0;
    cfg.attrs = attr;
    cfg.numAttrs = 1;
    cudaLaunchKernelEx(&cfg, kern, args...);
}

// ---------------------------------------------------------------------------
// launch
// Inputs (metadata order): col, values, adj, src_nodes,
//                          w1e, b1e, w2e, b2e, w1n, b1n, w2n, b2n
// ---------------------------------------------------------------------------
extern "C" void kernel_launch(void* const* d_in, const int* in_sizes, int n_in,
                              void* d_out, int out_size) {
    const int*   col       = (const int*)d_in[0];
    const float* values    = (const float*)d_in[1];
    const float* adj       = (const float*)d_in[2];
    const int*   src_nodes = (const int*)d_in[3];
    const float* w1e = (const float*)d_in[4];
    const float* b1e = (const float*)d_in[5];
    const float* w2e = (const float*)d_in[6];
    const float* b2e = (const float*)d_in[7];
    const float* w1n = (const float*)d_in[8];
    const float* b1n = (const float*)d_in[9];
    const float* w2n = (const float*)d_in[10];
    const float* b2n = (const float*)d_in[11];
    float* out = (float*)d_out;

    const int nnz = in_sizes[0];   // 262144
    const int E   = in_sizes[3];   // 32768

    // prefetch first (triggers immediately, so scatter overlaps it)
    k_prefetch<<<512, 256>>>(adj);

    // scatter: PDL, NO grid-sync inside (independent of prefetch)
    launch_pdl(k_edge_scatter, dim3((nnz + 255) / 256), dim3(256),
               col, values, w1e, b1e, w2e, b2e, nnz);

    // dependents: PDL with grid-sync
    launch_pdl(k_node_mlp, dim3((N_NODES + 511) / 512), dim3(512),
               w1n, b1n, w2n, b2n);
    launch_pdl(k_row_score, dim3(GRID_RS), dim3(256), adj);
    launch_pdl(k_gather, dim3((E + 255) / 256), dim3(256),
               src_nodes, out, E);
}